// round 2
// baseline (speedup 1.0000x reference)
#include <cuda_runtime.h>
#include <mma.h>
#include <math.h>

using namespace nvcuda;

// Problem dims: b=8, t=256, l=24, c=512, H=8, d=64
constexpr int ROWS = 49152;   // b*t*l
constexpr int C    = 512;
constexpr int L    = 24;
constexpr int NH   = 8;
constexpr int HD   = 64;

constexpr int BM = 128, BN = 64, BK = 16;
constexpr int A_LD = BK + 8;   // 24
constexpr int B_LD = BN + 8;   // 72
constexpr int O_LD = BN + 4;   // 68

// Scratch (device globals: allocation-free rule)
__device__ float g_qn[(size_t)ROWS * C];
__device__ float g_kn[(size_t)ROWS * C];
__device__ float g_vlin[(size_t)ROWS * C];
__device__ float g_vn[(size_t)ROWS * C];
__device__ float g_x[(size_t)ROWS * C];
__device__ float g_tanhv[L * C];

__global__ void tanh_kernel(const float* __restrict__ v_init) {
    int i = blockIdx.x * blockDim.x + threadIdx.x;
    if (i < L * C) g_tanhv[i] = tanhf(v_init[i]);
}

// EPI: 0 = q proj:  acc+bq  -> per-head L2 norm -> g_qn
//      1 = kv proj: cols<512: acc+bkv -> norm -> g_kn ; cols>=512: acc+bkv raw -> g_vlin
//      2 = gate:    A=g_vlin; relu(sigmoid(acc+bg)*tanhv) -> norm -> g_vn
//      3 = out:     A=g_x;    acc+bm+shortcut -> outp
template <int EPI, int NCOLS>
__global__ void __launch_bounds__(256) gemm_epi(
    const float* __restrict__ A_in, const float* __restrict__ W,
    const float* __restrict__ bias, const float* __restrict__ extra,
    float* __restrict__ outp)
{
    __shared__ float smem[BM * O_LD + BM];   // 35.3 KB; reused across phases
    float* As = smem;                        // BM*A_LD = 3072 floats
    float* Bs = smem + BM * A_LD;            // BK*B_LD = 1152 floats
    float* Os = smem;                        // epilogue tile (aliases As/Bs)
    float* rs = smem + BM * O_LD;            // 128 row scales

    const float* A = (EPI == 2) ? g_vlin : (EPI == 3) ? g_x : A_in;

    const int tid  = threadIdx.x;
    const int warp = tid >> 5;
    const int wm   = warp >> 1;   // 0..3
    const int wn   = warp & 1;    // 0..1
    const int m0   = blockIdx.y * BM;
    const int n0   = blockIdx.x * BN;

    wmma::fragment<wmma::accumulator, 16, 16, 8, float> acc[2][2];
    #pragma unroll
    for (int i = 0; i < 2; i++)
        #pragma unroll
        for (int j = 0; j < 2; j++)
            wmma::fill_fragment(acc[i][j], 0.0f);

    for (int k0 = 0; k0 < C; k0 += BK) {
        __syncthreads();
        // A tile: 128 x 16 (two float4 per thread)
        #pragma unroll
        for (int i = tid; i < BM * BK / 4; i += 256) {
            int r = i >> 2, c4 = (i & 3) * 4;
            float4 v = *reinterpret_cast<const float4*>(&A[(size_t)(m0 + r) * C + k0 + c4]);
            *reinterpret_cast<float4*>(&As[r * A_LD + c4]) = v;
        }
        // B tile: 16 x 64 (one float4 per thread)
        {
            int r = tid >> 4, c4 = (tid & 15) * 4;
            float4 v = *reinterpret_cast<const float4*>(&W[(size_t)(k0 + r) * NCOLS + n0 + c4]);
            *reinterpret_cast<float4*>(&Bs[r * B_LD + c4]) = v;
        }
        __syncthreads();

        #pragma unroll
        for (int ks = 0; ks < BK; ks += 8) {
            wmma::fragment<wmma::matrix_a, 16, 16, 8, wmma::precision::tf32, wmma::row_major> af[2];
            wmma::fragment<wmma::matrix_b, 16, 16, 8, wmma::precision::tf32, wmma::row_major> bf[2];
            #pragma unroll
            for (int mi = 0; mi < 2; mi++) {
                wmma::load_matrix_sync(af[mi], &As[(wm * 32 + mi * 16) * A_LD + ks], A_LD);
                #pragma unroll
                for (int e = 0; e < af[mi].num_elements; e++)
                    af[mi].x[e] = wmma::__float_to_tf32(af[mi].x[e]);
            }
            #pragma unroll
            for (int ni = 0; ni < 2; ni++) {
                wmma::load_matrix_sync(bf[ni], &Bs[ks * B_LD + wn * 32 + ni * 16], B_LD);
                #pragma unroll
                for (int e = 0; e < bf[ni].num_elements; e++)
                    bf[ni].x[e] = wmma::__float_to_tf32(bf[ni].x[e]);
            }
            #pragma unroll
            for (int mi = 0; mi < 2; mi++)
                #pragma unroll
                for (int ni = 0; ni < 2; ni++)
                    wmma::mma_sync(acc[mi][ni], af[mi], bf[ni], acc[mi][ni]);
        }
    }
    __syncthreads();

    #pragma unroll
    for (int mi = 0; mi < 2; mi++)
        #pragma unroll
        for (int ni = 0; ni < 2; ni++)
            wmma::store_matrix_sync(&Os[(wm * 32 + mi * 16) * O_LD + wn * 32 + ni * 16],
                                    acc[mi][ni], O_LD, wmma::mem_row_major);
    __syncthreads();

    if (EPI == 3) {
        for (int i = tid; i < BM * BN; i += 256) {
            int r = i >> 6, cc = i & 63;
            int gc = n0 + cc;
            size_t gi = (size_t)(m0 + r) * C + gc;
            outp[gi] = Os[r * O_LD + cc] + bias[gc] + extra[gi];
        }
        return;
    }
    if (EPI == 1 && n0 >= C) {
        for (int i = tid; i < BM * BN; i += 256) {
            int r = i >> 6, cc = i & 63;
            int gc = n0 + cc;
            g_vlin[(size_t)(m0 + r) * C + (gc - C)] = Os[r * O_LD + cc] + bias[gc];
        }
        return;
    }

    // bias / activation transform in place
    for (int i = tid; i < BM * BN; i += 256) {
        int r = i >> 6, cc = i & 63;
        int gc = n0 + cc;
        float v = Os[r * O_LD + cc] + bias[gc];
        if (EPI == 2) {
            float g  = 1.0f / (1.0f + expf(-v));
            float tv = g_tanhv[((m0 + r) % L) * C + gc];
            v = fmaxf(g * tv, 0.0f);
        }
        Os[r * O_LD + cc] = v;
    }
    __syncthreads();

    // per-head L2 norm: BN==64==head dim, n0 is 64-aligned -> whole head in tile
    if (tid < BM) {
        float s = 0.0f;
        #pragma unroll
        for (int cc = 0; cc < BN; cc++) {
            float v = Os[tid * O_LD + cc];
            s += v * v;
        }
        rs[tid] = 1.0f / fmaxf(sqrtf(s), 1e-12f);
    }
    __syncthreads();

    float* dst = (EPI == 0) ? g_qn : (EPI == 1) ? g_kn : g_vn;
    for (int i = tid; i < BM * BN; i += 256) {
        int r = i >> 6, cc = i & 63;
        dst[(size_t)(m0 + r) * C + n0 + cc] = Os[r * O_LD + cc] * rs[r];
    }
}

// One block per (b*t, head): 24x24 softmax attention over d=64.
__global__ void __launch_bounds__(128) attn_kernel() {
    __shared__ float qs[L * 65], ks_[L * 65], vs[L * 65], ps[L * 25];
    const int bt  = blockIdx.x;
    const int h   = blockIdx.y;
    const int tid = threadIdx.x;
    const size_t base = (size_t)bt * L;
    const int colb = h * HD;

    for (int i = tid; i < L * HD; i += 128) {
        int r = i / HD, cc = i % HD;
        size_t gi = (base + r) * C + colb + cc;
        qs[r * 65 + cc]  = g_qn[gi];
        ks_[r * 65 + cc] = g_kn[gi];
        vs[r * 65 + cc]  = g_vn[gi];
    }
    __syncthreads();

    for (int p = tid; p < L * L; p += 128) {
        int i = p / L, j = p % L;
        float s = 0.0f;
        #pragma unroll
        for (int kk = 0; kk < HD; kk++)
            s += qs[i * 65 + kk] * ks_[j * 65 + kk];
        ps[i * 25 + j] = s * 0.125f;   // 1/sqrt(64)
    }
    __syncthreads();

    if (tid < L) {
        float mx = -1e30f;
        #pragma unroll
        for (int j = 0; j < L; j++) mx = fmaxf(mx, ps[tid * 25 + j]);
        float sum = 0.0f;
        #pragma unroll
        for (int j = 0; j < L; j++) {
            float e = expf(ps[tid * 25 + j] - mx);
            ps[tid * 25 + j] = e;
            sum += e;
        }
        float inv = 1.0f / sum;
        #pragma unroll
        for (int j = 0; j < L; j++) ps[tid * 25 + j] *= inv;
    }
    __syncthreads();

    for (int p = tid; p < L * HD; p += 128) {
        int i = p / HD, dc = p % HD;
        float s = 0.0f;
        #pragma unroll
        for (int j = 0; j < L; j++)
            s += ps[i * 25 + j] * vs[j * 65 + dc];
        g_x[(base + i) * C + colb + dc] = s;
    }
}

extern "C" void kernel_launch(void* const* d_in, const int* in_sizes, int n_in,
                              void* d_out, int out_size) {
    const float* q     = (const float*)d_in[0];
    const float* kv    = (const float*)d_in[1];
    const float* Wq    = (const float*)d_in[2];
    const float* bq    = (const float*)d_in[3];
    const float* Wkv   = (const float*)d_in[4];
    const float* bkv   = (const float*)d_in[5];
    const float* Wg    = (const float*)d_in[6];
    const float* bg    = (const float*)d_in[7];
    const float* vinit = (const float*)d_in[8];
    const float* Wm    = (const float*)d_in[9];
    const float* bm    = (const float*)d_in[10];
    float* out = (float*)d_out;

    (void)in_sizes; (void)n_in; (void)out_size;

    tanh_kernel<<<(L * C + 255) / 256, 256>>>(vinit);

    // kv projection -> g_kn (normalized) + g_vlin
    gemm_epi<1, 2 * C><<<dim3(2 * C / BN, ROWS / BM), 256>>>(kv, Wkv, bkv, nullptr, nullptr);
    // q projection -> g_qn (normalized)
    gemm_epi<0, C><<<dim3(C / BN, ROWS / BM), 256>>>(q, Wq, bq, nullptr, nullptr);
    // gate -> g_vn (normalized)
    gemm_epi<2, C><<<dim3(C / BN, ROWS / BM), 256>>>(nullptr, Wg, bg, nullptr, nullptr);
    // attention -> g_x
    attn_kernel<<<dim3(ROWS / L, NH), 128>>>();
    // output projection + residual -> d_out
    gemm_epi<3, C><<<dim3(C / BN, ROWS / BM), 256>>>(nullptr, Wm, bm, q, out);
}

// round 14
// speedup vs baseline: 2.3388x; 2.3388x over previous
#include <cuda_runtime.h>
#include <cuda_bf16.h>
#include <mma.h>
#include <math.h>
#include <cstdint>

using namespace nvcuda;
typedef __nv_bfloat16 bf16;

// Problem dims: b=8, t=256, l=24, c=512, H=8, d=64
constexpr int ROWS = 49152;   // b*t*l
constexpr int C    = 512;
constexpr int L    = 24;
constexpr int NH   = 8;
constexpr int HD   = 64;

constexpr int BM = 128, BN = 128, BK = 32;
constexpr int A_LD = BK + 8;   // 40 bf16
constexpr int B_LD = BN + 8;   // 136 bf16
constexpr int O_LD = BN + 4;   // 132 floats
constexpr int NIT  = C / BK;   // 16

// smem byte offsets (mainloop buffers overlap epilogue tile)
constexpr int SM_A0 = 0;                      // 128*40*2  = 10240
constexpr int SM_A1 = 10240;                  //           = 10240
constexpr int SM_B0 = 20480;                  // 32*136*2  = 8704
constexpr int SM_B1 = 29184;                  // ends 37888
constexpr int SM_RS = BM * O_LD * 4;          // 67584 (Os = [0,67584))
constexpr int SM_TOTAL = SM_RS + BM * 2 * 4;  // 68608

// ---- device-global scratch (allocation-free rule) ----
__device__ bf16 g_qbf [(size_t)ROWS * C];
__device__ bf16 g_kvbf[(size_t)ROWS * C];
__device__ bf16 g_Wq [C * C];
__device__ bf16 g_Wkv[C * 2 * C];
__device__ bf16 g_Wg [C * C];
__device__ bf16 g_Wm [C * C];
__device__ bf16 g_qn  [(size_t)ROWS * C];
__device__ bf16 g_kn  [(size_t)ROWS * C];
__device__ bf16 g_vlin[(size_t)ROWS * C];
__device__ bf16 g_vn  [(size_t)ROWS * C];
__device__ bf16 g_x   [(size_t)ROWS * C];
__device__ float g_tanhv[L * C];

// ---- cp.async helpers ----
__device__ __forceinline__ void cp16(void* dst_smem, const void* src) {
    unsigned int d = (unsigned int)__cvta_generic_to_shared(dst_smem);
    asm volatile("cp.async.cg.shared.global [%0], [%1], 16;\n" :: "r"(d), "l"(src));
}
__device__ __forceinline__ void cp_commit() {
    asm volatile("cp.async.commit_group;\n");
}
template <int N>
__device__ __forceinline__ void cp_wait() {
    asm volatile("cp.async.wait_group %0;\n" :: "n"(N));
}

// ---- fp32 -> bf16 conversion into named globals ----
// T: 0=q, 1=kv, 2=Wq, 3=Wkv, 4=Wg, 5=Wm
template <int T>
__global__ void cvt_kernel(const float* __restrict__ src, int n) {
    bf16* dst = (T == 0) ? g_qbf : (T == 1) ? g_kvbf : (T == 2) ? g_Wq
              : (T == 3) ? g_Wkv : (T == 4) ? g_Wg : g_Wm;
    int i = (blockIdx.x * blockDim.x + threadIdx.x) * 4;
    if (i < n) {
        float4 v = *reinterpret_cast<const float4*>(src + i);
        dst[i + 0] = __float2bfloat16(v.x);
        dst[i + 1] = __float2bfloat16(v.y);
        dst[i + 2] = __float2bfloat16(v.z);
        dst[i + 3] = __float2bfloat16(v.w);
    }
}

__global__ void tanh_kernel(const float* __restrict__ v_init) {
    int i = blockIdx.x * blockDim.x + threadIdx.x;
    if (i < L * C) g_tanhv[i] = tanhf(v_init[i]);
}

// EPI: 0 = q proj:  acc+bq  -> per-head L2 norm -> g_qn
//      1 = kv proj: n0<512: acc+bkv -> norm -> g_kn ; n0>=512: acc+bkv -> g_vlin
//      2 = gate:    A=g_vlin; relu(sigmoid(acc+bg)*tanhv) -> norm -> g_vn
//      3 = out:     A=g_x;    acc+bm+shortcut -> outp (fp32)
template <int EPI, int NCOLS>
__global__ void __launch_bounds__(256) gemm_bf16(
    const float* __restrict__ bias, const float* __restrict__ extra,
    float* __restrict__ outp)
{
    extern __shared__ unsigned char sm[];
    bf16* Ab[2] = { (bf16*)(sm + SM_A0), (bf16*)(sm + SM_A1) };
    bf16* Bb[2] = { (bf16*)(sm + SM_B0), (bf16*)(sm + SM_B1) };
    float* Os = (float*)sm;
    float* rs = (float*)(sm + SM_RS);

    const bf16* A = (EPI == 0) ? g_qbf : (EPI == 1) ? g_kvbf
                  : (EPI == 2) ? g_vlin : g_x;
    const bf16* W = (EPI == 0) ? g_Wq : (EPI == 1) ? g_Wkv
                  : (EPI == 2) ? g_Wg : g_Wm;

    const int tid  = threadIdx.x;
    const int warp = tid >> 5;
    const int wm   = warp >> 2;   // 0..1  (64-row slabs)
    const int wn   = warp & 3;    // 0..3  (32-col slabs)
    const int m0   = blockIdx.y * BM;
    const int n0   = blockIdx.x * BN;

    wmma::fragment<wmma::accumulator, 16, 16, 16, float> acc[4][2];
    #pragma unroll
    for (int mi = 0; mi < 4; mi++)
        #pragma unroll
        for (int ni = 0; ni < 2; ni++)
            wmma::fill_fragment(acc[mi][ni], 0.0f);

    // tile loaders: 512 16B-chunks each, 2 per thread
    auto loadA = [&](int buf, int k0) {
        #pragma unroll
        for (int c = tid; c < 512; c += 256) {
            int r = c >> 2, q4 = c & 3;
            cp16(&Ab[buf][r * A_LD + q4 * 8],
                 &A[(size_t)(m0 + r) * C + k0 + q4 * 8]);
        }
    };
    auto loadB = [&](int buf, int k0) {
        #pragma unroll
        for (int c = tid; c < 512; c += 256) {
            int r = c >> 4, q8 = c & 15;
            cp16(&Bb[buf][r * B_LD + q8 * 8],
                 &W[(size_t)(k0 + r) * NCOLS + n0 + q8 * 8]);
        }
    };

    loadA(0, 0); loadB(0, 0); cp_commit();

    for (int it = 0; it < NIT; ++it) {
        if (it + 1 < NIT) {
            loadA((it + 1) & 1, (it + 1) * BK);
            loadB((it + 1) & 1, (it + 1) * BK);
            cp_commit();
            cp_wait<1>();
        } else {
            cp_wait<0>();
        }
        __syncthreads();

        bf16* As = Ab[it & 1];
        bf16* Bs = Bb[it & 1];
        #pragma unroll
        for (int ks = 0; ks < BK; ks += 16) {
            wmma::fragment<wmma::matrix_a, 16, 16, 16, bf16, wmma::row_major> af[4];
            wmma::fragment<wmma::matrix_b, 16, 16, 16, bf16, wmma::row_major> bfr[2];
            #pragma unroll
            for (int mi = 0; mi < 4; mi++)
                wmma::load_matrix_sync(af[mi], &As[(wm * 64 + mi * 16) * A_LD + ks], A_LD);
            #pragma unroll
            for (int ni = 0; ni < 2; ni++)
                wmma::load_matrix_sync(bfr[ni], &Bs[ks * B_LD + wn * 32 + ni * 16], B_LD);
            #pragma unroll
            for (int mi = 0; mi < 4; mi++)
                #pragma unroll
                for (int ni = 0; ni < 2; ni++)
                    wmma::mma_sync(acc[mi][ni], af[mi], bfr[ni], acc[mi][ni]);
        }
        __syncthreads();   // protect buf[it&1] from next iteration's prefetch
    }

    // ---- epilogue ----
    #pragma unroll
    for (int mi = 0; mi < 4; mi++)
        #pragma unroll
        for (int ni = 0; ni < 2; ni++)
            wmma::store_matrix_sync(&Os[(wm * 64 + mi * 16) * O_LD + wn * 32 + ni * 16],
                                    acc[mi][ni], O_LD, wmma::mem_row_major);
    __syncthreads();

    if (EPI == 3) {
        for (int i = tid; i < BM * BN; i += 256) {
            int r = i >> 7, cc = i & 127;
            int gc = n0 + cc;
            size_t gi = (size_t)(m0 + r) * C + gc;
            outp[gi] = Os[r * O_LD + cc] + bias[gc] + extra[gi];
        }
        return;
    }
    if (EPI == 1 && n0 >= C) {
        for (int i = tid; i < BM * BN; i += 256) {
            int r = i >> 7, cc = i & 127;
            int gc = n0 + cc;
            g_vlin[(size_t)(m0 + r) * C + (gc - C)] =
                __float2bfloat16(Os[r * O_LD + cc] + bias[gc]);
        }
        return;
    }

    // bias / activation in place
    for (int i = tid; i < BM * BN; i += 256) {
        int r = i >> 7, cc = i & 127;
        int gc = n0 + cc;
        float v = Os[r * O_LD + cc] + bias[gc];
        if (EPI == 2) {
            float g  = 1.0f / (1.0f + expf(-v));
            float tv = g_tanhv[((m0 + r) % L) * C + gc];
            v = fmaxf(g * tv, 0.0f);
        }
        Os[r * O_LD + cc] = v;
    }
    __syncthreads();

    // per-head L2 norm: two 64-col head groups per tile; 256 (row,grp) pairs
    {
        int r = tid >> 1, grp = tid & 1;
        float s = 0.0f;
        #pragma unroll
        for (int cc = 0; cc < HD; cc++) {
            float v = Os[r * O_LD + grp * HD + cc];
            s += v * v;
        }
        rs[r * 2 + grp] = 1.0f / fmaxf(sqrtf(s), 1e-12f);
    }
    __syncthreads();

    bf16* dst = (EPI == 0) ? g_qn : (EPI == 1) ? g_kn : g_vn;
    for (int i = tid; i < BM * BN; i += 256) {
        int r = i >> 7, cc = i & 127;
        float v = Os[r * O_LD + cc] * rs[r * 2 + (cc >> 6)];
        dst[(size_t)(m0 + r) * C + n0 + cc] = __float2bfloat16(v);
    }
}

// One block per (b*t, head): 24x24 softmax attention over d=64.
__global__ void __launch_bounds__(128) attn_kernel() {
    __shared__ float qs[L * 65], ks_[L * 65], vs[L * 65], ps[L * 25];
    const int bt  = blockIdx.x;
    const int h   = blockIdx.y;
    const int tid = threadIdx.x;
    const size_t base = (size_t)bt * L;
    const int colb = h * HD;

    for (int i = tid; i < L * HD; i += 128) {
        int r = i / HD, cc = i % HD;
        size_t gi = (base + r) * C + colb + cc;
        qs[r * 65 + cc]  = __bfloat162float(g_qn[gi]);
        ks_[r * 65 + cc] = __bfloat162float(g_kn[gi]);
        vs[r * 65 + cc]  = __bfloat162float(g_vn[gi]);
    }
    __syncthreads();

    for (int p = tid; p < L * L; p += 128) {
        int i = p / L, j = p % L;
        float s = 0.0f;
        #pragma unroll
        for (int kk = 0; kk < HD; kk++)
            s += qs[i * 65 + kk] * ks_[j * 65 + kk];
        ps[i * 25 + j] = s * 0.125f;   // 1/sqrt(64)
    }
    __syncthreads();

    if (tid < L) {
        float mx = -1e30f;
        #pragma unroll
        for (int j = 0; j < L; j++) mx = fmaxf(mx, ps[tid * 25 + j]);
        float sum = 0.0f;
        #pragma unroll
        for (int j = 0; j < L; j++) {
            float e = expf(ps[tid * 25 + j] - mx);
            ps[tid * 25 + j] = e;
            sum += e;
        }
        float inv = 1.0f / sum;
        #pragma unroll
        for (int j = 0; j < L; j++) ps[tid * 25 + j] *= inv;
    }
    __syncthreads();

    for (int p = tid; p < L * HD; p += 128) {
        int i = p / HD, dc = p % HD;
        float s = 0.0f;
        #pragma unroll
        for (int j = 0; j < L; j++)
            s += ps[i * 25 + j] * vs[j * 65 + dc];
        g_x[(base + i) * C + colb + dc] = __float2bfloat16(s);
    }
}

extern "C" void kernel_launch(void* const* d_in, const int* in_sizes, int n_in,
                              void* d_out, int out_size) {
    const float* q     = (const float*)d_in[0];
    const float* kv    = (const float*)d_in[1];
    const float* Wq    = (const float*)d_in[2];
    const float* bq    = (const float*)d_in[3];
    const float* Wkv   = (const float*)d_in[4];
    const float* bkv   = (const float*)d_in[5];
    const float* Wg    = (const float*)d_in[6];
    const float* bg    = (const float*)d_in[7];
    const float* vinit = (const float*)d_in[8];
    const float* Wm    = (const float*)d_in[9];
    const float* bm    = (const float*)d_in[10];
    float* out = (float*)d_out;
    (void)in_sizes; (void)n_in; (void)out_size;

    // opt-in to 68KB dynamic smem (idempotent host calls; not allocations)
    cudaFuncSetAttribute(gemm_bf16<0, C>,     cudaFuncAttributeMaxDynamicSharedMemorySize, SM_TOTAL);
    cudaFuncSetAttribute(gemm_bf16<1, 2 * C>, cudaFuncAttributeMaxDynamicSharedMemorySize, SM_TOTAL);
    cudaFuncSetAttribute(gemm_bf16<2, C>,     cudaFuncAttributeMaxDynamicSharedMemorySize, SM_TOTAL);
    cudaFuncSetAttribute(gemm_bf16<3, C>,     cudaFuncAttributeMaxDynamicSharedMemorySize, SM_TOTAL);

    const int NA = ROWS * C;   // 25165824
    cvt_kernel<0><<<NA / 4 / 256, 256>>>(q,  NA);
    cvt_kernel<1><<<NA / 4 / 256, 256>>>(kv, NA);
    cvt_kernel<2><<<C * C / 4 / 256, 256>>>(Wq,  C * C);
    cvt_kernel<3><<<C * 2 * C / 4 / 256, 256>>>(Wkv, C * 2 * C);
    cvt_kernel<4><<<C * C / 4 / 256, 256>>>(Wg,  C * C);
    cvt_kernel<5><<<C * C / 4 / 256, 256>>>(Wm,  C * C);
    tanh_kernel<<<(L * C + 255) / 256, 256>>>(vinit);

    // kv projection -> g_kn (normalized) + g_vlin
    gemm_bf16<1, 2 * C><<<dim3(2 * C / BN, ROWS / BM), 256, SM_TOTAL>>>(bkv, nullptr, nullptr);
    // q projection -> g_qn (normalized)
    gemm_bf16<0, C><<<dim3(C / BN, ROWS / BM), 256, SM_TOTAL>>>(bq, nullptr, nullptr);
    // gate -> g_vn (normalized)
    gemm_bf16<2, C><<<dim3(C / BN, ROWS / BM), 256, SM_TOTAL>>>(bg, nullptr, nullptr);
    // attention -> g_x
    attn_kernel<<<dim3(ROWS / L, NH), 128>>>();
    // output projection + residual -> d_out
    gemm_bf16<3, C><<<dim3(C / BN, ROWS / BM), 256, SM_TOTAL>>>(bm, q, out);
}